// round 2
// baseline (speedup 1.0000x reference)
#include <cuda_runtime.h>
#include <cfloat>
#include <climits>

// Problem constants
#define B_ 32768
#define D_ 512
#define L_ 4
#define K_ 1024

// Screening GEMM tiling
#define BM 64
#define BN 128
#define BK 32

// Safety margin for exact-rescore triggering (fine-score units).
#define ETA 2e-2f

// Scratch (no allocations allowed -> __device__ globals)
__device__ float g_residual[(size_t)B_ * D_];   // 64 MB
__device__ float g_c2[L_ * K_];
__device__ float g_top1s[B_];
__device__ float g_top2s[B_];
__device__ int   g_top1i[B_];
__device__ float g_rowss[L_ * B_];

typedef unsigned long long u64;

// Packed dual fp32 FMA (Blackwell f32x2 pipe): d = a*b + d (2 lanes)
__device__ __forceinline__ void ffma2(u64& d, u64 a, u64 b) {
    asm("fma.rn.f32x2 %0,%1,%2,%3;" : "=l"(d) : "l"(a), "l"(b), "l"(d));
}
__device__ __forceinline__ void unpack2(u64 v, float& x, float& y) {
    asm("mov.b64 {%0,%1},%2;" : "=f"(x), "=f"(y) : "l"(v));
}

// top-2 insert with lowest-index tie-break
__device__ __forceinline__ void top2_insert(float s, int i,
                                            float& b1, int& i1,
                                            float& b2, int& i2) {
    if (s < b1 || (s == b1 && i < i1)) {
        b2 = b1; i2 = i1; b1 = s; i1 = i;
    } else if (s < b2 || (s == b2 && i < i2)) {
        b2 = s; i2 = i;
    }
}

// ||c||^2 per codeword: fp64 accumulate, round to fp32. One warp per codeword.
__global__ void c2_kernel(const float* __restrict__ cb) {
    int g = blockIdx.x * blockDim.x + threadIdx.x;
    int w = g >> 5, lane = g & 31;
    if (w >= L_ * K_) return;
    const float* row = cb + (size_t)w * D_;
    double s = 0.0;
    #pragma unroll 4
    for (int d = lane; d < D_; d += 32) { double v = (double)row[d]; s = fma(v, v, s); }
    #pragma unroll
    for (int o = 16; o; o >>= 1) s += __shfl_xor_sync(0xffffffffu, s, o);
    if (!lane) g_c2[w] = (float)s;
}

// Fused fp32 GEMM + per-row top-2. Fine score s[b,k] = ||c_k||^2 - 2 <r_b, c_k>.
__global__ __launch_bounds__(256, 2) void screen_kernel(const float* __restrict__ z,
                                                        const float* __restrict__ cb,
                                                        int level) {
    __shared__ __align__(16) float2 As2[BK][BM + 2];   // duplicated-pair A
    __shared__ __align__(16) float  Bs[BK][BN + 4];
    __shared__ float rbS1[BM], rbS2[BM];
    __shared__ int   rbI1[BM], rbI2[BM];

    const float* R   = level ? g_residual : z;
    const float* cbl = cb + (size_t)level * K_ * D_;
    const float* c2l = g_c2 + level * K_;

    const int tid = threadIdx.x;
    const int tx = tid & 15, ty = tid >> 4;
    const int m0 = blockIdx.x * BM;
    const int r0 = ty << 2, n0 = tx << 3;

    if (tid < BM) {
        rbS1[tid] = FLT_MAX; rbS2[tid] = FLT_MAX;
        rbI1[tid] = INT_MAX; rbI2[tid] = INT_MAX;
    }

    for (int nt = 0; nt < K_ / BN; nt++) {
        u64 acc[4][4];
        #pragma unroll
        for (int i = 0; i < 4; i++)
            #pragma unroll
            for (int j = 0; j < 4; j++) acc[i][j] = 0ull;

        for (int kt = 0; kt < D_ / BK; kt++) {
            const int k0 = kt * BK;
            // Stage A transposed + duplicated: As2[k][m] = (a, a)
            #pragma unroll
            for (int v = 0; v < 2; v++) {
                int li = tid + v * 256;
                int row = li >> 3, kq = (li & 7) << 2;
                float4 a = *reinterpret_cast<const float4*>(
                    R + (size_t)(m0 + row) * D_ + k0 + kq);
                As2[kq + 0][row] = make_float2(a.x, a.x);
                As2[kq + 1][row] = make_float2(a.y, a.y);
                As2[kq + 2][row] = make_float2(a.z, a.z);
                As2[kq + 3][row] = make_float2(a.w, a.w);
            }
            // Stage B transposed: Bs[k][n]
            #pragma unroll
            for (int v = 0; v < 4; v++) {
                int li = tid + v * 256;
                int nl = li >> 3, kq = (li & 7) << 2;
                float4 b = *reinterpret_cast<const float4*>(
                    cbl + (size_t)(nt * BN + nl) * D_ + k0 + kq);
                Bs[kq + 0][nl] = b.x; Bs[kq + 1][nl] = b.y;
                Bs[kq + 2][nl] = b.z; Bs[kq + 3][nl] = b.w;
            }
            __syncthreads();
            #pragma unroll
            for (int kk = 0; kk < BK; kk++) {
                ulonglong2 a01 = *reinterpret_cast<const ulonglong2*>(&As2[kk][r0]);
                ulonglong2 a23 = *reinterpret_cast<const ulonglong2*>(&As2[kk][r0 + 2]);
                ulonglong2 b01 = *reinterpret_cast<const ulonglong2*>(&Bs[kk][n0]);
                ulonglong2 b23 = *reinterpret_cast<const ulonglong2*>(&Bs[kk][n0 + 4]);
                u64 ad[4] = { a01.x, a01.y, a23.x, a23.y };
                u64 bq[4] = { b01.x, b01.y, b23.x, b23.y };
                #pragma unroll
                for (int i = 0; i < 4; i++)
                    #pragma unroll
                    for (int j = 0; j < 4; j++) ffma2(acc[i][j], ad[i], bq[j]);
            }
            __syncthreads();
        }

        // Epilogue: fine scores + per-row top-2 (lowest-index tie-break)
        float c2r[8];
        #pragma unroll
        for (int j = 0; j < 8; j++) c2r[j] = __ldg(c2l + nt * BN + n0 + j);
        #pragma unroll
        for (int i = 0; i < 4; i++) {
            float b1 = FLT_MAX, b2 = FLT_MAX; int i1 = INT_MAX, i2 = INT_MAX;
            #pragma unroll
            for (int jp = 0; jp < 4; jp++) {
                float d0, d1; unpack2(acc[i][jp], d0, d1);
                int n = nt * BN + n0 + jp * 2;
                float s0 = fmaf(-2.f, d0, c2r[jp * 2 + 0]);
                float s1 = fmaf(-2.f, d1, c2r[jp * 2 + 1]);
                top2_insert(s0, n,     b1, i1, b2, i2);
                top2_insert(s1, n + 1, b1, i1, b2, i2);
            }
            #pragma unroll
            for (int o = 8; o; o >>= 1) {
                float o1 = __shfl_xor_sync(0xffffffffu, b1, o);
                int   q1 = __shfl_xor_sync(0xffffffffu, i1, o);
                float o2 = __shfl_xor_sync(0xffffffffu, b2, o);
                int   q2 = __shfl_xor_sync(0xffffffffu, i2, o);
                top2_insert(o1, q1, b1, i1, b2, i2);
                top2_insert(o2, q2, b1, i1, b2, i2);
            }
            if (tx == 0) {   // unique owner thread per row slot
                int r = r0 + i;
                float s1h = rbS1[r], s2h = rbS2[r];
                int   i1h = rbI1[r], i2h = rbI2[r];
                top2_insert(b1, i1, s1h, i1h, s2h, i2h);
                top2_insert(b2, i2, s1h, i1h, s2h, i2h);
                rbS1[r] = s1h; rbS2[r] = s2h; rbI1[r] = i1h; rbI2[r] = i2h;
            }
        }
        __syncthreads();
    }
    if (tid < BM) {
        g_top1s[m0 + tid] = rbS1[tid];
        g_top2s[m0 + tid] = rbS2[tid];
        g_top1i[m0 + tid] = rbI1[tid];
    }
}

// Decide final index (exact rescore when ambiguous), then gather + update.
// One warp per row.
__global__ void update_kernel(const float* __restrict__ z,
                              const float* __restrict__ cb,
                              float* __restrict__ lv_base,
                              int level) {
    int g = blockIdx.x * blockDim.x + threadIdx.x;
    int w = g >> 5, lane = g & 31;
    if (w >= B_) return;
    const float* prevres = level ? g_residual : z;
    const float* rrow = prevres + (size_t)w * D_;
    const float* cbl  = cb + (size_t)level * K_ * D_;
    const float* c2l  = g_c2 + level * K_;
    float* lv_out = lv_base + (size_t)level * B_ * D_;

    int idx = g_top1i[w];
    if (g_top2s[w] - g_top1s[w] < ETA) {
        // fp64 rescan emulating reference's fp32 rounding chain:
        // S = fl32( fl32(r2 - 2*fl32(dot)) + c2 ), lowest-index tie-break.
        double rd[16]; double r2d = 0.0;
        #pragma unroll
        for (int j = 0; j < 16; j++) {
            double v = (double)rrow[j * 32 + lane];
            rd[j] = v; r2d = fma(v, v, r2d);
        }
        #pragma unroll
        for (int o = 16; o; o >>= 1) r2d += __shfl_xor_sync(0xffffffffu, r2d, o);
        float r2f = (float)r2d;

        float best = FLT_MAX; int bidx = 0;
        for (int k = 0; k < K_; k++) {
            const float* crow = cbl + (size_t)k * D_;
            double dp = 0.0;
            #pragma unroll
            for (int j = 0; j < 16; j++) dp = fma(rd[j], (double)crow[j * 32 + lane], dp);
            #pragma unroll
            for (int o = 16; o; o >>= 1) dp += __shfl_xor_sync(0xffffffffu, dp, o);
            float m = (float)dp;
            float S = __fadd_rn(__fsub_rn(r2f, __fmul_rn(2.0f, m)), __ldg(c2l + k));
            if (S < best) { best = S; bidx = k; }  // strict <, ascending k
        }
        idx = bidx;
    }

    const float4* c  = reinterpret_cast<const float4*>(cbl + (size_t)idx * D_);
    const float4* r  = reinterpret_cast<const float4*>(rrow);
    float4* ro = reinterpret_cast<float4*>(g_residual + (size_t)w * D_);
    float4* lo = reinterpret_cast<float4*>(lv_out + (size_t)w * D_);
    float ss = 0.f;
    #pragma unroll
    for (int d = lane; d < D_ / 4; d += 32) {
        float4 rv = r[d], cv = c[d];
        float4 nv = make_float4(rv.x - cv.x, rv.y - cv.y, rv.z - cv.z, rv.w - cv.w);
        ro[d] = nv;
        lo[d] = cv;
        ss = fmaf(nv.x, nv.x, fmaf(nv.y, nv.y, fmaf(nv.z, nv.z, fmaf(nv.w, nv.w, ss))));
    }
    #pragma unroll
    for (int o = 16; o; o >>= 1) ss += __shfl_xor_sync(0xffffffffu, ss, o);
    if (!lane) g_rowss[level * B_ + w] = ss;
}

// quantized = z - residual_final
__global__ void quant_kernel(const float* __restrict__ z, float* __restrict__ outq) {
    size_t i = (size_t)blockIdx.x * blockDim.x + threadIdx.x;
    const float4* zv = reinterpret_cast<const float4*>(z);
    const float4* rv = reinterpret_cast<const float4*>(g_residual);
    float4* o = reinterpret_cast<float4*>(outq);
    float4 a = zv[i], b = rv[i];
    o[i] = make_float4(a.x - b.x, a.y - b.y, a.z - b.z, a.w - b.w);
}

// rq_loss = sum_l fl32(mean(residual_l^2)), fp32 level-order accumulation.
__global__ void loss_kernel(float* __restrict__ out) {
    __shared__ double sh[256];
    __shared__ float means[L_];
    int t = threadIdx.x;
    for (int l = 0; l < L_; l++) {
        double s = 0.0;
        for (int i = t; i < B_; i += 256) s += (double)g_rowss[l * B_ + i];
        sh[t] = s; __syncthreads();
        for (int o = 128; o; o >>= 1) { if (t < o) sh[t] += sh[t + o]; __syncthreads(); }
        if (t == 0) means[l] = (float)(sh[0] / ((double)B_ * (double)D_));
        __syncthreads();
    }
    if (t == 0) {
        float loss = 0.f;
        for (int l = 0; l < L_; l++) loss = __fadd_rn(loss, means[l]);
        out[0] = loss;
    }
}

extern "C" void kernel_launch(void* const* d_in, const int* in_sizes, int n_in,
                              void* d_out, int out_size) {
    const float* z  = (const float*)d_in[0];   // [B, D]
    const float* cb = (const float*)d_in[1];   // [L, K, D]
    float* out = (float*)d_out;
    float* outq  = out;                                       // quantized [B, D]
    float* outlv = out + (size_t)B_ * D_;                     // all_level_vectors [L, B, D]
    float* outls = out + (size_t)B_ * D_ * (size_t)(1 + L_);  // rq_loss scalar

    c2_kernel<<<(L_ * K_ * 32) / 256, 256>>>(cb);

    for (int l = 0; l < L_; l++) {
        screen_kernel<<<B_ / BM, 256>>>(z, cb, l);
        update_kernel<<<(B_ * 32) / 256, 256>>>(z, cb, outlv, l);
    }

    quant_kernel<<<(B_ * D_ / 4) / 256, 256>>>(z, outq);
    loss_kernel<<<1, 256>>>(outls);
}

// round 4
// speedup vs baseline: 18.8844x; 18.8844x over previous
#include <cuda_runtime.h>
#include <cuda_bf16.h>
#include <cfloat>
#include <climits>
#include <cstdint>

// Problem constants
#define B_ 32768
#define D_ 512
#define L_ 4
#define K_ 1024

// Candidate margin for bf16 screening (score units). bf16 dot noise sigma ~0.05.
#define MARGIN 0.35f

// ---------------- scratch (__device__ globals; no allocations allowed) -----------
__device__ float          g_residual[(size_t)B_ * D_];   // fp32 residual, 64 MB
__device__ __nv_bfloat16  g_rb[(size_t)B_ * D_];         // bf16 residual (GEMM A), 32 MB
__device__ __nv_bfloat16  g_cbh[(size_t)L_ * K_ * D_];   // bf16 codebooks, 4 MB
__device__ float          g_dot[(size_t)B_ * K_];        // raw fp32 dots, 128 MB
__device__ float          g_c2[L_ * K_];
__device__ int            g_idx[B_];
__device__ float          g_rowss[L_ * B_];

__device__ __forceinline__ uint32_t smem_u32(const void* p) {
    uint32_t a;
    asm("{ .reg .u64 t; cvta.to.shared.u64 t, %1; cvt.u32.u64 %0, t; }" : "=r"(a) : "l"(p));
    return a;
}

// ---------------- prep kernels ---------------------------------------------------
__global__ void conv_z_kernel(const float* __restrict__ z) {
    size_t i = ((size_t)blockIdx.x * blockDim.x + threadIdx.x) * 8;
    float4 a = *reinterpret_cast<const float4*>(z + i);
    float4 b = *reinterpret_cast<const float4*>(z + i + 4);
    __nv_bfloat162 h[4] = { __floats2bfloat162_rn(a.x, a.y), __floats2bfloat162_rn(a.z, a.w),
                            __floats2bfloat162_rn(b.x, b.y), __floats2bfloat162_rn(b.z, b.w) };
    *reinterpret_cast<uint4*>(g_rb + i) = *reinterpret_cast<uint4*>(h);
}

__global__ void conv_cb_kernel(const float* __restrict__ cb) {
    size_t i = ((size_t)blockIdx.x * blockDim.x + threadIdx.x) * 8;
    float4 a = *reinterpret_cast<const float4*>(cb + i);
    float4 b = *reinterpret_cast<const float4*>(cb + i + 4);
    __nv_bfloat162 h[4] = { __floats2bfloat162_rn(a.x, a.y), __floats2bfloat162_rn(a.z, a.w),
                            __floats2bfloat162_rn(b.x, b.y), __floats2bfloat162_rn(b.z, b.w) };
    *reinterpret_cast<uint4*>(g_cbh + i) = *reinterpret_cast<uint4*>(h);
}

// ||c||^2: fp64 accumulate -> fp32. One warp per codeword.
__global__ void c2_kernel(const float* __restrict__ cb) {
    int g = blockIdx.x * blockDim.x + threadIdx.x;
    int w = g >> 5, lane = g & 31;
    if (w >= L_ * K_) return;
    const float* row = cb + (size_t)w * D_;
    double s = 0.0;
    #pragma unroll 4
    for (int d = lane; d < D_; d += 32) { double v = (double)row[d]; s = fma(v, v, s); }
    #pragma unroll
    for (int o = 16; o; o >>= 1) s += __shfl_xor_sync(0xffffffffu, s, o);
    if (!lane) g_c2[w] = (float)s;
}

// ---------------- bf16 screening GEMM via ldmatrix + mma.sync (HMMA) -------------
// Per CTA: 128 rows x all 1024 codes, K=512. Raw dots -> g_dot.
// smem: A tile 128x512 bf16 (128 KB, XOR-swizzled 16B chunks) + B double buffer
// (2 x 128 codes x 128 k = 2 x 32 KB).
#define SM_A     0
#define SM_B     131072
#define SM_BBUF  32768
#define SM_TOTAL (131072 + 2 * 32768)

__device__ __forceinline__ void ldsm_x4(uint32_t* r, uint32_t addr) {
    asm volatile("ldmatrix.sync.aligned.m8n8.x4.shared.b16 {%0,%1,%2,%3}, [%4];"
        : "=r"(r[0]), "=r"(r[1]), "=r"(r[2]), "=r"(r[3]) : "r"(addr));
}
__device__ __forceinline__ void mma16816(float* c, const uint32_t* a, uint32_t b0, uint32_t b1) {
    asm volatile("mma.sync.aligned.m16n8k16.row.col.f32.bf16.bf16.f32 "
        "{%0,%1,%2,%3}, {%4,%5,%6,%7}, {%8,%9}, {%0,%1,%2,%3};"
        : "+f"(c[0]), "+f"(c[1]), "+f"(c[2]), "+f"(c[3])
        : "r"(a[0]), "r"(a[1]), "r"(a[2]), "r"(a[3]), "r"(b0), "r"(b1));
}

__global__ __launch_bounds__(256, 1) void gemm_kernel(int level) {
    extern __shared__ char smem[];
    const int tid = threadIdx.x, wid = tid >> 5, lane = tid & 31;
    const int m0 = blockIdx.x * 128;
    const __nv_bfloat16* Bsrc = g_cbh + (size_t)level * K_ * D_;
    const uint32_t sb = smem_u32(smem);

    // Stage A: 128 rows x 512 bf16. 16B chunk (m, c): addr = m*1024 + (c^(m&7))*16
    #pragma unroll
    for (int i = 0; i < 32; i++) {
        int q = tid + i * 256;
        int m = q >> 6, c = q & 63;
        uint4 v = *reinterpret_cast<const uint4*>(g_rb + (size_t)(m0 + m) * D_ + c * 8);
        *reinterpret_cast<uint4*>(smem + SM_A + m * 1024 + ((c ^ (m & 7)) * 16)) = v;
    }

    // B chunk cid in 0..31: nt = cid>>2, kc = cid&3. 128 codes x 128 k, cp.async.
    #define LOAD_B_CHUNK(cid, buf) do {                                              \
        int _nt = (cid) >> 2, _kc = (cid) & 3;                                       \
        const __nv_bfloat16* _src = Bsrc + (size_t)_nt * 128 * D_ + _kc * 128;       \
        _Pragma("unroll")                                                            \
        for (int _i = 0; _i < 8; _i++) {                                             \
            int _q = tid + _i * 256;                                                 \
            int _n = _q >> 4, _c = _q & 15;                                          \
            uint32_t _dst = sb + SM_B + (buf) * SM_BBUF + _n * 256 +                 \
                            ((_c ^ (_n & 7)) * 16);                                  \
            const void* _g = _src + (size_t)_n * D_ + _c * 8;                        \
            asm volatile("cp.async.cg.shared.global [%0], [%1], 16;"                 \
                         :: "r"(_dst), "l"(_g));                                     \
        }                                                                            \
        asm volatile("cp.async.commit_group;");                                      \
    } while (0)

    const int wm = wid & 3, wn = wid >> 2;   // warp tile: rows wm*32..+31, cols wn*64..+63
    const int lr = lane & 7;                 // row within 8x8 tile
    const int lh = (lane >> 3) & 1;          // half selector
    const int lk = lane >> 4;                // quad selector

    LOAD_B_CHUNK(0, 0);

    float acc[2][8][4];

    for (int cid = 0; cid < 32; cid++) {
        const int buf = cid & 1;
        if (cid + 1 < 32) {
            LOAD_B_CHUNK(cid + 1, buf ^ 1);
            asm volatile("cp.async.wait_group 1;");
        } else {
            asm volatile("cp.async.wait_group 0;");
        }
        __syncthreads();
        const int nt = cid >> 2, kc = cid & 3;

        if (kc == 0) {
            #pragma unroll
            for (int mt = 0; mt < 2; mt++)
                #pragma unroll
                for (int nti = 0; nti < 8; nti++)
                    #pragma unroll
                    for (int q = 0; q < 4; q++) acc[mt][nti][q] = 0.f;
        }

        #pragma unroll
        for (int ks = 0; ks < 8; ks++) {
            // A fragments: 2 m-tiles of 16x16 at k = kc*128 + ks*16
            uint32_t a[2][4];
            #pragma unroll
            for (int mt = 0; mt < 2; mt++) {
                int m = wm * 32 + mt * 16 + lh * 8 + lr;
                int ch = (kc * 16) + (ks * 2) + lk;   // global 16B-chunk index (k/8)
                uint32_t addr = sb + SM_A + m * 1024 + ((ch ^ (m & 7)) * 16);
                ldsm_x4(a[mt], addr);
            }
            // B fragments: 4 pairs of n8 tiles (covers 64 cols) at local k = ks*16
            uint32_t b[4][4];
            #pragma unroll
            for (int p = 0; p < 4; p++) {
                int n = wn * 64 + p * 16 + lk * 8 + lr;
                int ch = ks * 2 + lh;                 // local 16B-chunk (of 16)
                uint32_t addr = sb + SM_B + buf * SM_BBUF + n * 256 + ((ch ^ (n & 7)) * 16);
                ldsm_x4(b[p], addr);
            }
            #pragma unroll
            for (int mt = 0; mt < 2; mt++)
                #pragma unroll
                for (int nti = 0; nti < 8; nti++)
                    mma16816(acc[mt][nti], a[mt],
                             b[nti >> 1][(nti & 1) * 2 + 0],
                             b[nti >> 1][(nti & 1) * 2 + 1]);
        }

        if (kc == 3) {   // epilogue: write raw dots for this 128-col tile
            #pragma unroll
            for (int mt = 0; mt < 2; mt++) {
                int row = m0 + wm * 32 + mt * 16 + (lane >> 2);
                #pragma unroll
                for (int nti = 0; nti < 8; nti++) {
                    int col = nt * 128 + wn * 64 + nti * 8 + (lane & 3) * 2;
                    *reinterpret_cast<float2*>(g_dot + (size_t)row * K_ + col) =
                        make_float2(acc[mt][nti][0], acc[mt][nti][1]);
                    *reinterpret_cast<float2*>(g_dot + (size_t)(row + 8) * K_ + col) =
                        make_float2(acc[mt][nti][2], acc[mt][nti][3]);
                }
            }
        }
        __syncthreads();   // protect buffer reuse + A tile vs next staging
    }
    #undef LOAD_B_CHUNK
}

// ---------------- argmin + exact rescore -----------------------------------------
// One warp per row. Candidates within MARGIN of screened min; single => winner.
__global__ __launch_bounds__(256) void argmin_kernel(const float* __restrict__ z,
                                                     const float* __restrict__ cb,
                                                     int level) {
    __shared__ int cnt[8];
    __shared__ int cand[8][32];
    const int tid = threadIdx.x, wid = tid >> 5, lane = tid & 31;
    const int b = blockIdx.x * 8 + wid;
    const float* R   = level ? g_residual : z;
    const float* cbl = cb + (size_t)level * K_ * D_;
    const float* c2l = g_c2 + level * K_;
    const float* drow = g_dot + (size_t)b * K_;

    float s[32];
    float best = FLT_MAX;
    #pragma unroll
    for (int j = 0; j < 8; j++) {
        float4 dv = *reinterpret_cast<const float4*>(drow + j * 128 + lane * 4);
        float4 cv = *reinterpret_cast<const float4*>(c2l + j * 128 + lane * 4);
        s[j * 4 + 0] = fmaf(-2.f, dv.x, cv.x);
        s[j * 4 + 1] = fmaf(-2.f, dv.y, cv.y);
        s[j * 4 + 2] = fmaf(-2.f, dv.z, cv.z);
        s[j * 4 + 3] = fmaf(-2.f, dv.w, cv.w);
        best = fminf(best, fminf(fminf(s[j*4+0], s[j*4+1]), fminf(s[j*4+2], s[j*4+3])));
    }
    #pragma unroll
    for (int o = 16; o; o >>= 1) best = fminf(best, __shfl_xor_sync(0xffffffffu, best, o));

    if (lane == 0) cnt[wid] = 0;
    __syncwarp();
    const float thr = best + MARGIN;
    #pragma unroll
    for (int j = 0; j < 8; j++)
        #pragma unroll
        for (int q = 0; q < 4; q++)
            if (s[j * 4 + q] <= thr) {
                int p = atomicAdd(&cnt[wid], 1);
                if (p < 32) cand[wid][p] = j * 128 + lane * 4 + q;
            }
    __syncwarp();
    int n = cnt[wid];
    int idx;
    if (n == 1) {
        idx = cand[wid][0];
    } else {
        // exact: fp64 dot + the reference's fp32 rounding chain
        double rd[16]; double r2 = 0.0;
        const float* rrow = R + (size_t)b * D_;
        #pragma unroll
        for (int j = 0; j < 16; j++) {
            double v = (double)rrow[j * 32 + lane];
            rd[j] = v; r2 = fma(v, v, r2);
        }
        #pragma unroll
        for (int o = 16; o; o >>= 1) r2 += __shfl_xor_sync(0xffffffffu, r2, o);
        float r2f = (float)r2;

        float bestS = FLT_MAX; int bi = INT_MAX;
        if (n <= 32) {
            for (int t = 0; t < n; t++) {
                int k = cand[wid][t];
                const float* crow = cbl + (size_t)k * D_;
                double dp0 = 0.0, dp1 = 0.0;
                #pragma unroll
                for (int j = 0; j < 16; j += 2) {
                    dp0 = fma(rd[j],     (double)crow[j * 32 + lane],       dp0);
                    dp1 = fma(rd[j + 1], (double)crow[(j + 1) * 32 + lane], dp1);
                }
                double dp = dp0 + dp1;
                #pragma unroll
                for (int o = 16; o; o >>= 1) dp += __shfl_xor_sync(0xffffffffu, dp, o);
                float S = __fadd_rn(__fsub_rn(r2f, __fmul_rn(2.0f, (float)dp)), __ldg(c2l + k));
                if (S < bestS || (S == bestS && k < bi)) { bestS = S; bi = k; }
            }
        } else {
            for (int k = 0; k < K_; k++) {      // overflow fallback (≈never)
                const float* crow = cbl + (size_t)k * D_;
                double dp0 = 0.0, dp1 = 0.0;
                #pragma unroll
                for (int j = 0; j < 16; j += 2) {
                    dp0 = fma(rd[j],     (double)crow[j * 32 + lane],       dp0);
                    dp1 = fma(rd[j + 1], (double)crow[(j + 1) * 32 + lane], dp1);
                }
                double dp = dp0 + dp1;
                #pragma unroll
                for (int o = 16; o; o >>= 1) dp += __shfl_xor_sync(0xffffffffu, dp, o);
                float S = __fadd_rn(__fsub_rn(r2f, __fmul_rn(2.0f, (float)dp)), __ldg(c2l + k));
                if (S < bestS) { bestS = S; bi = k; }
            }
        }
        idx = bi;
    }
    if (lane == 0) g_idx[b] = idx;
}

// ---------------- residual update (fp32 + bf16 mirror) ---------------------------
__global__ void update_kernel(const float* __restrict__ z,
                              const float* __restrict__ cb,
                              float* __restrict__ lv_base,
                              int level) {
    int g = blockIdx.x * blockDim.x + threadIdx.x;
    int w = g >> 5, lane = g & 31;
    const float* prevres = level ? g_residual : z;
    const float* cbl = cb + (size_t)level * K_ * D_;
    int idx = g_idx[w];

    const float4* c  = reinterpret_cast<const float4*>(cbl + (size_t)idx * D_);
    const float4* r  = reinterpret_cast<const float4*>(prevres + (size_t)w * D_);
    float4* ro = reinterpret_cast<float4*>(g_residual + (size_t)w * D_);
    float4* lo = reinterpret_cast<float4*>(lv_base + (size_t)level * B_ * D_ + (size_t)w * D_);
    float ss = 0.f;
    #pragma unroll
    for (int d = lane; d < D_ / 4; d += 32) {
        float4 rv = r[d], cv = c[d];
        float4 nv = make_float4(rv.x - cv.x, rv.y - cv.y, rv.z - cv.z, rv.w - cv.w);
        ro[d] = nv;
        lo[d] = cv;
        __nv_bfloat162 h0 = __floats2bfloat162_rn(nv.x, nv.y);
        __nv_bfloat162 h1 = __floats2bfloat162_rn(nv.z, nv.w);
        uint2 pk = make_uint2(*reinterpret_cast<uint32_t*>(&h0), *reinterpret_cast<uint32_t*>(&h1));
        *reinterpret_cast<uint2*>(g_rb + (size_t)w * D_ + d * 4) = pk;
        ss = fmaf(nv.x, nv.x, fmaf(nv.y, nv.y, fmaf(nv.z, nv.z, fmaf(nv.w, nv.w, ss))));
    }
    #pragma unroll
    for (int o = 16; o; o >>= 1) ss += __shfl_xor_sync(0xffffffffu, ss, o);
    if (!lane) g_rowss[level * B_ + w] = ss;
}

// ---------------- outputs --------------------------------------------------------
__global__ void quant_kernel(const float* __restrict__ z, float* __restrict__ outq) {
    size_t i = (size_t)blockIdx.x * blockDim.x + threadIdx.x;
    const float4* zv = reinterpret_cast<const float4*>(z);
    const float4* rv = reinterpret_cast<const float4*>(g_residual);
    float4* o = reinterpret_cast<float4*>(outq);
    float4 a = zv[i], b = rv[i];
    o[i] = make_float4(a.x - b.x, a.y - b.y, a.z - b.z, a.w - b.w);
}

__global__ void loss_kernel(float* __restrict__ out) {
    __shared__ double sh[256];
    __shared__ float means[L_];
    int t = threadIdx.x;
    for (int l = 0; l < L_; l++) {
        double s = 0.0;
        for (int i = t; i < B_; i += 256) s += (double)g_rowss[l * B_ + i];
        sh[t] = s; __syncthreads();
        for (int o = 128; o; o >>= 1) { if (t < o) sh[t] += sh[t + o]; __syncthreads(); }
        if (t == 0) means[l] = (float)(sh[0] / ((double)B_ * (double)D_));
        __syncthreads();
    }
    if (t == 0) {
        float loss = 0.f;
        for (int l = 0; l < L_; l++) loss = __fadd_rn(loss, means[l]);
        out[0] = loss;
    }
}

// ---------------- launcher -------------------------------------------------------
extern "C" void kernel_launch(void* const* d_in, const int* in_sizes, int n_in,
                              void* d_out, int out_size) {
    const float* z  = (const float*)d_in[0];   // [B, D]
    const float* cb = (const float*)d_in[1];   // [L, K, D]
    float* out = (float*)d_out;
    float* outq  = out;
    float* outlv = out + (size_t)B_ * D_;
    float* outls = out + (size_t)B_ * D_ * (size_t)(1 + L_);

    static bool attr_set = false;
    if (!attr_set) {
        cudaFuncSetAttribute(gemm_kernel, cudaFuncAttributeMaxDynamicSharedMemorySize, SM_TOTAL);
        attr_set = true;
    }

    conv_z_kernel<<<(B_ * D_ / 8) / 256, 256>>>(z);
    conv_cb_kernel<<<(L_ * K_ * D_ / 8) / 256, 256>>>(cb);
    c2_kernel<<<(L_ * K_ * 32) / 256, 256>>>(cb);

    for (int l = 0; l < L_; l++) {
        gemm_kernel<<<B_ / 128, 256, SM_TOTAL>>>(l);
        argmin_kernel<<<B_ / 8, 256>>>(z, cb, l);
        update_kernel<<<(B_ * 32) / 256, 256>>>(z, cb, outlv, l);
    }

    quant_kernel<<<(B_ * D_ / 4) / 256, 256>>>(z, outq);
    loss_kernel<<<1, 256>>>(outls);
}

// round 5
// speedup vs baseline: 23.6519x; 1.2525x over previous
#include <cuda_runtime.h>
#include <cuda_bf16.h>
#include <cuda_fp16.h>
#include <cfloat>
#include <climits>
#include <cstdint>

// Problem constants
#define B_ 32768
#define D_ 512
#define L_ 4
#define K_ 1024

// Candidate margin (score units). Screened-score error bound ~0.07 (bf16 GEMM
// noise + fp16 score storage); 0.15 > 2x bound => n==1 winner is provable and
// the true argmin is always captured for rescore.
#define MARGIN 0.15f

// ---------------- scratch (__device__ globals; no allocations allowed) -----------
__device__ float          g_residual[(size_t)B_ * D_];   // fp32 residual, 64 MB
__device__ __nv_bfloat16  g_rb[(size_t)B_ * D_];         // bf16 residual (GEMM A), 32 MB
__device__ __nv_bfloat16  g_cbh[(size_t)L_ * K_ * D_];   // bf16 codebooks, 4 MB
__device__ __half         g_sc[(size_t)B_ * K_];         // fp16 screened scores, 64 MB
__device__ float          g_c2[L_ * K_];
__device__ float          g_rowss[L_ * B_];

__device__ __forceinline__ uint32_t smem_u32(const void* p) {
    uint32_t a;
    asm("{ .reg .u64 t; cvta.to.shared.u64 t, %1; cvt.u32.u64 %0, t; }" : "=r"(a) : "l"(p));
    return a;
}

// ---------------- prep kernels ---------------------------------------------------
__global__ void conv_z_kernel(const float* __restrict__ z) {
    size_t i = ((size_t)blockIdx.x * blockDim.x + threadIdx.x) * 8;
    float4 a = *reinterpret_cast<const float4*>(z + i);
    float4 b = *reinterpret_cast<const float4*>(z + i + 4);
    __nv_bfloat162 h[4] = { __floats2bfloat162_rn(a.x, a.y), __floats2bfloat162_rn(a.z, a.w),
                            __floats2bfloat162_rn(b.x, b.y), __floats2bfloat162_rn(b.z, b.w) };
    *reinterpret_cast<uint4*>(g_rb + i) = *reinterpret_cast<uint4*>(h);
}

__global__ void conv_cb_kernel(const float* __restrict__ cb) {
    size_t i = ((size_t)blockIdx.x * blockDim.x + threadIdx.x) * 8;
    float4 a = *reinterpret_cast<const float4*>(cb + i);
    float4 b = *reinterpret_cast<const float4*>(cb + i + 4);
    __nv_bfloat162 h[4] = { __floats2bfloat162_rn(a.x, a.y), __floats2bfloat162_rn(a.z, a.w),
                            __floats2bfloat162_rn(b.x, b.y), __floats2bfloat162_rn(b.z, b.w) };
    *reinterpret_cast<uint4*>(g_cbh + i) = *reinterpret_cast<uint4*>(h);
}

// ||c||^2: fp64 accumulate -> fp32. One warp per codeword.
__global__ void c2_kernel(const float* __restrict__ cb) {
    int g = blockIdx.x * blockDim.x + threadIdx.x;
    int w = g >> 5, lane = g & 31;
    if (w >= L_ * K_) return;
    const float* row = cb + (size_t)w * D_;
    double s = 0.0;
    #pragma unroll 4
    for (int d = lane; d < D_; d += 32) { double v = (double)row[d]; s = fma(v, v, s); }
    #pragma unroll
    for (int o = 16; o; o >>= 1) s += __shfl_xor_sync(0xffffffffu, s, o);
    if (!lane) g_c2[w] = (float)s;
}

// ---------------- bf16 screening GEMM + fused score epilogue ---------------------
// Per CTA: 128 rows x all 1024 codes, K=512. fp16 scores (c2 - 2*dot) -> g_sc.
// 512 threads, 16 warps, warp tile 32x32.
#define SM_A     0
#define SM_B     131072
#define SM_BBUF  32768
#define SM_TOTAL (131072 + 2 * 32768)

__device__ __forceinline__ void ldsm_x4(uint32_t* r, uint32_t addr) {
    asm volatile("ldmatrix.sync.aligned.m8n8.x4.shared.b16 {%0,%1,%2,%3}, [%4];"
        : "=r"(r[0]), "=r"(r[1]), "=r"(r[2]), "=r"(r[3]) : "r"(addr));
}
__device__ __forceinline__ void mma16816(float* c, const uint32_t* a, uint32_t b0, uint32_t b1) {
    asm volatile("mma.sync.aligned.m16n8k16.row.col.f32.bf16.bf16.f32 "
        "{%0,%1,%2,%3}, {%4,%5,%6,%7}, {%8,%9}, {%0,%1,%2,%3};"
        : "+f"(c[0]), "+f"(c[1]), "+f"(c[2]), "+f"(c[3])
        : "r"(a[0]), "r"(a[1]), "r"(a[2]), "r"(a[3]), "r"(b0), "r"(b1));
}

__global__ __launch_bounds__(512, 1) void gemm_kernel(int level) {
    extern __shared__ char smem[];
    const int tid = threadIdx.x, wid = tid >> 5, lane = tid & 31;
    const int m0 = blockIdx.x * 128;
    const __nv_bfloat16* Bsrc = g_cbh + (size_t)level * K_ * D_;
    const float* c2l = g_c2 + level * K_;
    const uint32_t sb = smem_u32(smem);

    // Stage A via cp.async: 128 rows x 512 bf16, XOR-swizzled 16B chunks.
    #pragma unroll
    for (int i = 0; i < 16; i++) {
        int q = tid + i * 512;
        int m = q >> 6, c = q & 63;
        uint32_t dst = sb + SM_A + m * 1024 + ((c ^ (m & 7)) * 16);
        const void* g = g_rb + (size_t)(m0 + m) * D_ + c * 8;
        asm volatile("cp.async.cg.shared.global [%0], [%1], 16;" :: "r"(dst), "l"(g));
    }
    asm volatile("cp.async.commit_group;");

    // B chunk cid in 0..31: nt = cid>>2, kc = cid&3. 128 codes x 128 k.
    #define LOAD_B_CHUNK(cid, buf) do {                                              \
        int _nt = (cid) >> 2, _kc = (cid) & 3;                                       \
        const __nv_bfloat16* _src = Bsrc + (size_t)_nt * 128 * D_ + _kc * 128;       \
        _Pragma("unroll")                                                            \
        for (int _i = 0; _i < 4; _i++) {                                             \
            int _q = tid + _i * 512;                                                 \
            int _n = _q >> 4, _c = _q & 15;                                          \
            uint32_t _dst = sb + SM_B + (buf) * SM_BBUF + _n * 256 +                 \
                            ((_c ^ (_n & 7)) * 16);                                  \
            const void* _g = _src + (size_t)_n * D_ + _c * 8;                        \
            asm volatile("cp.async.cg.shared.global [%0], [%1], 16;"                 \
                         :: "r"(_dst), "l"(_g));                                     \
        }                                                                            \
        asm volatile("cp.async.commit_group;");                                      \
    } while (0)

    const int wm = wid & 3, wn = wid >> 2;   // warp tile: rows wm*32..+31, cols wn*32..+31
    const int lr = lane & 7;
    const int lh = (lane >> 3) & 1;
    const int lk = lane >> 4;

    LOAD_B_CHUNK(0, 0);

    float acc[2][4][4];

    for (int cid = 0; cid < 32; cid++) {
        const int buf = cid & 1;
        if (cid + 1 < 32) {
            LOAD_B_CHUNK(cid + 1, buf ^ 1);
            asm volatile("cp.async.wait_group 1;");
        } else {
            asm volatile("cp.async.wait_group 0;");
        }
        __syncthreads();
        const int nt = cid >> 2, kc = cid & 3;

        if (kc == 0) {
            #pragma unroll
            for (int mt = 0; mt < 2; mt++)
                #pragma unroll
                for (int nti = 0; nti < 4; nti++)
                    #pragma unroll
                    for (int q = 0; q < 4; q++) acc[mt][nti][q] = 0.f;
        }

        #pragma unroll
        for (int ks = 0; ks < 8; ks++) {
            uint32_t a[2][4];
            #pragma unroll
            for (int mt = 0; mt < 2; mt++) {
                int m = wm * 32 + mt * 16 + lh * 8 + lr;
                int ch = (kc * 16) + (ks * 2) + lk;
                uint32_t addr = sb + SM_A + m * 1024 + ((ch ^ (m & 7)) * 16);
                ldsm_x4(a[mt], addr);
            }
            uint32_t b[2][4];
            #pragma unroll
            for (int p = 0; p < 2; p++) {
                int n = wn * 32 + p * 16 + lk * 8 + lr;
                int ch = ks * 2 + lh;
                uint32_t addr = sb + SM_B + buf * SM_BBUF + n * 256 + ((ch ^ (n & 7)) * 16);
                ldsm_x4(b[p], addr);
            }
            #pragma unroll
            for (int mt = 0; mt < 2; mt++)
                #pragma unroll
                for (int nti = 0; nti < 4; nti++)
                    mma16816(acc[mt][nti], a[mt],
                             b[nti >> 1][(nti & 1) * 2 + 0],
                             b[nti >> 1][(nti & 1) * 2 + 1]);
        }

        if (kc == 3) {   // fused epilogue: fp16 scores for this 128-col tile
            #pragma unroll
            for (int mt = 0; mt < 2; mt++) {
                int row = m0 + wm * 32 + mt * 16 + (lane >> 2);
                #pragma unroll
                for (int nti = 0; nti < 4; nti++) {
                    int col = nt * 128 + wn * 32 + nti * 8 + (lane & 3) * 2;
                    float2 cv = *reinterpret_cast<const float2*>(c2l + col);
                    __half2 h0 = __floats2half2_rn(fmaf(-2.f, acc[mt][nti][0], cv.x),
                                                   fmaf(-2.f, acc[mt][nti][1], cv.y));
                    __half2 h1 = __floats2half2_rn(fmaf(-2.f, acc[mt][nti][2], cv.x),
                                                   fmaf(-2.f, acc[mt][nti][3], cv.y));
                    *reinterpret_cast<__half2*>(g_sc + (size_t)row * K_ + col) = h0;
                    *reinterpret_cast<__half2*>(g_sc + (size_t)(row + 8) * K_ + col) = h1;
                }
            }
        }
        __syncthreads();
    }
    #undef LOAD_B_CHUNK
}

// ---------------- fused argmin + exact rescore + residual update -----------------
// One warp per row. Reads fp16 scores; n==1 candidate => provably correct winner;
// else fp64-exact rescore of candidates (reference fp32 rounding chain).
// Then updates residual, writes level vec, bf16 mirror (levels 0-2), per-row
// sumsq, and at level 3 also quantized = z - residual.
__global__ __launch_bounds__(256) void argmin_update_kernel(const float* __restrict__ z,
                                                            const float* __restrict__ cb,
                                                            float* __restrict__ lv_base,
                                                            float* __restrict__ outq,
                                                            int level) {
    __shared__ int cnt[8];
    __shared__ int cand[8][32];
    const int tid = threadIdx.x, wid = tid >> 5, lane = tid & 31;
    const int b = blockIdx.x * 8 + wid;
    const float* prevres = level ? g_residual : z;
    const float* rrow = prevres + (size_t)b * D_;
    const float* cbl = cb + (size_t)level * K_ * D_;
    const float* c2l = g_c2 + level * K_;
    const __half2* srow = reinterpret_cast<const __half2*>(g_sc + (size_t)b * K_);

    // Load scores: k = j*64 + lane*2 + {0,1}
    float s[32];
    float best = FLT_MAX;
    #pragma unroll
    for (int j = 0; j < 16; j++) {
        float2 v = __half22float2(srow[j * 32 + lane]);
        s[j * 2 + 0] = v.x; s[j * 2 + 1] = v.y;
        best = fminf(best, fminf(v.x, v.y));
    }
    #pragma unroll
    for (int o = 16; o; o >>= 1) best = fminf(best, __shfl_xor_sync(0xffffffffu, best, o));

    if (lane == 0) cnt[wid] = 0;
    __syncwarp();
    const float thr = best + MARGIN;
    #pragma unroll
    for (int j = 0; j < 16; j++)
        #pragma unroll
        for (int q = 0; q < 2; q++)
            if (s[j * 2 + q] <= thr) {
                int p = atomicAdd(&cnt[wid], 1);
                if (p < 32) cand[wid][p] = j * 64 + lane * 2 + q;
            }
    __syncwarp();
    int n = cnt[wid];
    int idx;
    if (n == 1) {
        idx = cand[wid][0];
    } else {
        // exact: fp64 dot + the reference's fp32 rounding chain
        double rd[16]; double r2 = 0.0;
        #pragma unroll
        for (int j = 0; j < 16; j++) {
            double v = (double)rrow[j * 32 + lane];
            rd[j] = v; r2 = fma(v, v, r2);
        }
        #pragma unroll
        for (int o = 16; o; o >>= 1) r2 += __shfl_xor_sync(0xffffffffu, r2, o);
        float r2f = (float)r2;

        float bestS = FLT_MAX; int bi = INT_MAX;
        if (n <= 32) {
            for (int t = 0; t < n; t++) {
                int k = cand[wid][t];
                const float* crow = cbl + (size_t)k * D_;
                double dp0 = 0.0, dp1 = 0.0;
                #pragma unroll
                for (int j = 0; j < 16; j += 2) {
                    dp0 = fma(rd[j],     (double)crow[j * 32 + lane],       dp0);
                    dp1 = fma(rd[j + 1], (double)crow[(j + 1) * 32 + lane], dp1);
                }
                double dp = dp0 + dp1;
                #pragma unroll
                for (int o = 16; o; o >>= 1) dp += __shfl_xor_sync(0xffffffffu, dp, o);
                float S = __fadd_rn(__fsub_rn(r2f, __fmul_rn(2.0f, (float)dp)), __ldg(c2l + k));
                if (S < bestS || (S == bestS && k < bi)) { bestS = S; bi = k; }
            }
        } else {
            for (int k = 0; k < K_; k++) {      // overflow fallback (~never)
                const float* crow = cbl + (size_t)k * D_;
                double dp0 = 0.0, dp1 = 0.0;
                #pragma unroll
                for (int j = 0; j < 16; j += 2) {
                    dp0 = fma(rd[j],     (double)crow[j * 32 + lane],       dp0);
                    dp1 = fma(rd[j + 1], (double)crow[(j + 1) * 32 + lane], dp1);
                }
                double dp = dp0 + dp1;
                #pragma unroll
                for (int o = 16; o; o >>= 1) dp += __shfl_xor_sync(0xffffffffu, dp, o);
                float S = __fadd_rn(__fsub_rn(r2f, __fmul_rn(2.0f, (float)dp)), __ldg(c2l + k));
                if (S < bestS) { bestS = S; bi = k; }
            }
        }
        idx = bi;
    }

    // ---- update phase ----
    const float4* c  = reinterpret_cast<const float4*>(cbl + (size_t)idx * D_);
    const float4* r  = reinterpret_cast<const float4*>(rrow);
    float4* ro = reinterpret_cast<float4*>(g_residual + (size_t)b * D_);
    float4* lo = reinterpret_cast<float4*>(lv_base + (size_t)level * B_ * D_ + (size_t)b * D_);
    const float4* zv = reinterpret_cast<const float4*>(z + (size_t)b * D_);
    float4* oq = reinterpret_cast<float4*>(outq + (size_t)b * D_);
    float ss = 0.f;
    #pragma unroll
    for (int d = lane; d < D_ / 4; d += 32) {
        float4 rv = r[d], cv = c[d];
        float4 nv = make_float4(rv.x - cv.x, rv.y - cv.y, rv.z - cv.z, rv.w - cv.w);
        ro[d] = nv;
        lo[d] = cv;
        if (level < 3) {
            __nv_bfloat162 h0 = __floats2bfloat162_rn(nv.x, nv.y);
            __nv_bfloat162 h1 = __floats2bfloat162_rn(nv.z, nv.w);
            uint2 pk = make_uint2(*reinterpret_cast<uint32_t*>(&h0),
                                  *reinterpret_cast<uint32_t*>(&h1));
            *reinterpret_cast<uint2*>(g_rb + (size_t)b * D_ + d * 4) = pk;
        } else {
            float4 zq = zv[d];
            oq[d] = make_float4(zq.x - nv.x, zq.y - nv.y, zq.z - nv.z, zq.w - nv.w);
        }
        ss = fmaf(nv.x, nv.x, fmaf(nv.y, nv.y, fmaf(nv.z, nv.z, fmaf(nv.w, nv.w, ss))));
    }
    #pragma unroll
    for (int o = 16; o; o >>= 1) ss += __shfl_xor_sync(0xffffffffu, ss, o);
    if (!lane) g_rowss[level * B_ + b] = ss;
}

// ---------------- loss -----------------------------------------------------------
__global__ void loss_kernel(float* __restrict__ out) {
    __shared__ double sh[256];
    __shared__ float means[L_];
    int t = threadIdx.x;
    for (int l = 0; l < L_; l++) {
        double s = 0.0;
        for (int i = t; i < B_; i += 256) s += (double)g_rowss[l * B_ + i];
        sh[t] = s; __syncthreads();
        for (int o = 128; o; o >>= 1) { if (t < o) sh[t] += sh[t + o]; __syncthreads(); }
        if (t == 0) means[l] = (float)(sh[0] / ((double)B_ * (double)D_));
        __syncthreads();
    }
    if (t == 0) {
        float loss = 0.f;
        for (int l = 0; l < L_; l++) loss = __fadd_rn(loss, means[l]);
        out[0] = loss;
    }
}

// ---------------- launcher -------------------------------------------------------
extern "C" void kernel_launch(void* const* d_in, const int* in_sizes, int n_in,
                              void* d_out, int out_size) {
    const float* z  = (const float*)d_in[0];   // [B, D]
    const float* cb = (const float*)d_in[1];   // [L, K, D]
    float* out = (float*)d_out;
    float* outq  = out;
    float* outlv = out + (size_t)B_ * D_;
    float* outls = out + (size_t)B_ * D_ * (size_t)(1 + L_);

    static bool attr_set = false;
    if (!attr_set) {
        cudaFuncSetAttribute(gemm_kernel, cudaFuncAttributeMaxDynamicSharedMemorySize, SM_TOTAL);
        attr_set = true;
    }

    conv_z_kernel<<<(B_ * D_ / 8) / 256, 256>>>(z);
    conv_cb_kernel<<<(L_ * K_ * D_ / 8) / 256, 256>>>(cb);
    c2_kernel<<<(L_ * K_ * 32) / 256, 256>>>(cb);

    for (int l = 0; l < L_; l++) {
        gemm_kernel<<<B_ / 128, 512, SM_TOTAL>>>(l);
        argmin_update_kernel<<<B_ / 8, 256>>>(z, cb, outlv, outq, l);
    }

    loss_kernel<<<1, 256>>>(outls);
}